// round 3
// baseline (speedup 1.0000x reference)
#include <cuda_runtime.h>
#include <math.h>

#define MDIM 4096
#define CDIM 1024
#define T_SEQ 2048
#define N_H 16
#define D_HEAD 64

typedef unsigned int u32;

// Scratch (device globals; allocation-free per harness rules)
__device__ u32 g_xt[MDIM * CDIM];        // x in tf32
__device__ u32 g_wt[4][CDIM * CDIM];     // Wq,Wk,Wv,Wo transposed [n][k] tf32
__device__ u32 g_q[MDIM * CDIM];         // tf32, pre-scaled by 0.125
__device__ u32 g_k[MDIM * CDIM];         // tf32
__device__ u32 g_v[MDIM * CDIM];         // tf32
__device__ u32 g_y[MDIM * CDIM];         // tf32

// ---------------------------------------------------------------------------
// helpers
// ---------------------------------------------------------------------------
__device__ __forceinline__ u32 f2tf(float f) {
    u32 r;
    asm("cvt.rna.tf32.f32 %0, %1;" : "=r"(r) : "f"(f));
    return r;
}

__device__ __forceinline__ void mma8(float* d, const u32* a, const u32* b) {
    asm volatile(
        "mma.sync.aligned.m16n8k8.row.col.f32.tf32.tf32.f32 "
        "{%0,%1,%2,%3}, {%4,%5,%6,%7}, {%8,%9}, {%0,%1,%2,%3};"
        : "+f"(d[0]), "+f"(d[1]), "+f"(d[2]), "+f"(d[3])
        : "r"(a[0]), "r"(a[1]), "r"(a[2]), "r"(a[3]), "r"(b[0]), "r"(b[1]));
}

__device__ __forceinline__ void ldsm4(u32& r0, u32& r1, u32& r2, u32& r3, u32 addr) {
    asm volatile("ldmatrix.sync.aligned.m8n8.x4.shared.b16 {%0,%1,%2,%3}, [%4];"
                 : "=r"(r0), "=r"(r1), "=r"(r2), "=r"(r3) : "r"(addr));
}

__device__ __forceinline__ void cp16(u32 dst, const void* src) {
    asm volatile("cp.async.cg.shared.global [%0], [%1], 16;" :: "r"(dst), "l"(src));
}
#define CP_COMMIT() asm volatile("cp.async.commit_group;")
#define CP_WAIT(n)  asm volatile("cp.async.wait_group %0;" :: "n"(n))

// ---------------------------------------------------------------------------
// prep kernels: convert x to tf32; transpose+convert weights to [n][k] tf32
// ---------------------------------------------------------------------------
__global__ __launch_bounds__(256) void prep_x_kernel(const float* __restrict__ x)
{
    const float4* src = (const float4*)x;
    uint4* dst = (uint4*)g_xt;
    const int n4 = MDIM * CDIM / 4;
    for (int i = blockIdx.x * blockDim.x + threadIdx.x; i < n4;
         i += gridDim.x * blockDim.x) {
        float4 v = src[i];
        uint4 o;
        o.x = f2tf(v.x); o.y = f2tf(v.y); o.z = f2tf(v.z); o.w = f2tf(v.w);
        dst[i] = o;
    }
}

__global__ __launch_bounds__(256) void prep_w_kernel(const float* __restrict__ Wq,
                                                     const float* __restrict__ Wk,
                                                     const float* __restrict__ Wv,
                                                     const float* __restrict__ Wo)
{
    const int z = blockIdx.z;
    const float* W = (z == 0) ? Wq : (z == 1) ? Wk : (z == 2) ? Wv : Wo;
    u32* D = g_wt[z];
    __shared__ float t[32][33];
    const int n0 = blockIdx.x * 32, k0 = blockIdx.y * 32;
    const int tx = threadIdx.x, ty = threadIdx.y;  // 32 x 8
#pragma unroll
    for (int i = 0; i < 32; i += 8)
        t[ty + i][tx] = W[(size_t)(k0 + ty + i) * CDIM + n0 + tx];  // t[k][n]
    __syncthreads();
#pragma unroll
    for (int i = 0; i < 32; i += 8)
        D[(size_t)(n0 + ty + i) * CDIM + k0 + tx] = f2tf(t[tx][ty + i]);
}

// ---------------------------------------------------------------------------
// tf32 GEMM: C[4096,1024] = A[4096,1024] @ Bt[n][k]^T  (A,Bt already tf32)
// 128x128 tile, ktile 32, 3-stage cp.async, ldmatrix frags, 256 thr (8 warps 4x2)
// ---------------------------------------------------------------------------
#define A_LD 36
#define STG_U32 (128 * A_LD)                    // 4608 u32 per operand per stage
#define GEMM_SMEM_BYTES (3 * 2 * STG_U32 * 4)   // 110592 B

__device__ __forceinline__ void gemm_issue(u32 sA, u32 sB, const u32* Ag,
                                           const u32* Bg, int kt)
{
    const u32* a = Ag + kt * 32;
    const u32* b = Bg + kt * 32;
#pragma unroll
    for (int i = 0; i < 4; i++) {
        cp16(sA + 16 * i, a + 4 * i);
        cp16(sB + 16 * i, b + 4 * i);
    }
}

// OUT_MODE 0: float out + bias; 1: tf32 u32 out scaled by oscale
template <int OUT_MODE>
__device__ __forceinline__ void gemm_core(const u32* __restrict__ A,
                                          const u32* __restrict__ Bt,
                                          const float* __restrict__ bias,
                                          void* __restrict__ Cv, float oscale)
{
    extern __shared__ u32 sm[];
    const u32 smbase = (u32)__cvta_generic_to_shared(sm);

    const int tid = threadIdx.x;
    const int lane = tid & 31;
    const int warp = tid >> 5;
    const int wm = warp >> 1;
    const int wn = warp & 1;
    const int row0 = blockIdx.y * 128;
    const int col0 = blockIdx.x * 128;

    // loader mapping
    const int l_row = tid >> 1;
    const int l_kq = (tid & 1) * 16;
    const u32* Ag = A + (size_t)(row0 + l_row) * CDIM + l_kq;
    const u32* Bg = Bt + (size_t)(col0 + l_row) * CDIM + l_kq;
    const u32 sOff = (l_row * A_LD + l_kq) * 4;

    // ldmatrix lane mapping
    const int lrow = (lane & 7) | ((lane & 16) >> 1);
    const int lcol = (lane & 8) >> 1;
    const u32 a_f0 = (u32)((wm * 32 + lrow) * A_LD + lcol);
    const u32 b_f0 = (u32)((wn * 64 + lrow) * A_LD + lcol);

    float acc[2][8][4];
#pragma unroll
    for (int mt = 0; mt < 2; mt++)
#pragma unroll
        for (int nt = 0; nt < 8; nt++)
#pragma unroll
            for (int i = 0; i < 4; i++) acc[mt][nt][i] = 0.f;

    // prologue: stages 0,1
    gemm_issue(smbase + sOff, smbase + STG_U32 * 4 + sOff, Ag, Bg, 0);
    CP_COMMIT();
    gemm_issue(smbase + 2 * STG_U32 * 4 + sOff, smbase + 3 * STG_U32 * 4 + sOff, Ag, Bg, 1);
    CP_COMMIT();

    for (int kt = 0; kt < 32; kt++) {
        CP_WAIT(1);
        __syncthreads();
        if (kt + 2 < 32) {
            const int s = (kt + 2) % 3;
            gemm_issue(smbase + (u32)(s * 2 * STG_U32) * 4 + sOff,
                       smbase + (u32)((s * 2 + 1) * STG_U32) * 4 + sOff, Ag, Bg, kt + 2);
        }
        CP_COMMIT();

        const int buf = kt % 3;
        const u32 abase = smbase + (u32)(buf * 2 * STG_U32 + a_f0) * 4;
        const u32 bbase = smbase + (u32)((buf * 2 + 1) * STG_U32 + b_f0) * 4;
#pragma unroll
        for (int kk = 0; kk < 4; kk++) {
            u32 af[2][4];
#pragma unroll
            for (int mt = 0; mt < 2; mt++) {
                u32 r0, r1, r2, r3;
                ldsm4(r0, r1, r2, r3, abase + (u32)(mt * 16 * A_LD + kk * 8) * 4);
                af[mt][0] = r0; af[mt][1] = r2; af[mt][2] = r1; af[mt][3] = r3;
            }
            u32 bf[8][2];
#pragma unroll
            for (int ntp = 0; ntp < 4; ntp++) {
                u32 r0, r1, r2, r3;
                ldsm4(r0, r1, r2, r3, bbase + (u32)(ntp * 16 * A_LD + kk * 8) * 4);
                bf[2 * ntp][0] = r0; bf[2 * ntp][1] = r1;
                bf[2 * ntp + 1][0] = r2; bf[2 * ntp + 1][1] = r3;
            }
#pragma unroll
            for (int nt = 0; nt < 8; nt++)
#pragma unroll
                for (int mt = 0; mt < 2; mt++)
                    mma8(acc[mt][nt], af[mt], bf[nt]);
        }
    }

    // epilogue
    const int g = lane >> 2, t4 = lane & 3;
#pragma unroll
    for (int mt = 0; mt < 2; mt++) {
#pragma unroll
        for (int nt = 0; nt < 8; nt++) {
            const int r = row0 + wm * 32 + mt * 16 + g;
            const int c = col0 + wn * 64 + nt * 8 + t4 * 2;
            if (OUT_MODE == 0) {
                float* C = (float*)Cv;
                const float b0 = bias[c], b1 = bias[c + 1];
                *(float2*)(C + (size_t)r * CDIM + c) =
                    make_float2(acc[mt][nt][0] + b0, acc[mt][nt][1] + b1);
                *(float2*)(C + (size_t)(r + 8) * CDIM + c) =
                    make_float2(acc[mt][nt][2] + b0, acc[mt][nt][3] + b1);
            } else {
                u32* C = (u32*)Cv;
                uint2 v0, v1;
                v0.x = f2tf(acc[mt][nt][0] * oscale);
                v0.y = f2tf(acc[mt][nt][1] * oscale);
                v1.x = f2tf(acc[mt][nt][2] * oscale);
                v1.y = f2tf(acc[mt][nt][3] * oscale);
                *(uint2*)(C + (size_t)r * CDIM + c) = v0;
                *(uint2*)(C + (size_t)(r + 8) * CDIM + c) = v1;
            }
        }
    }
}

__global__ __launch_bounds__(256) void qkv_gemm_kernel()
{
    const int z = blockIdx.z;
    u32* C = (z == 0) ? g_q : (z == 1) ? g_k : g_v;
    const float oscale = (z == 0) ? 0.125f : 1.0f;
    gemm_core<1>(g_xt, g_wt[z], nullptr, C, oscale);
}

__global__ __launch_bounds__(256) void out_gemm_kernel(const float* __restrict__ bo,
                                                       float* __restrict__ out)
{
    gemm_core<0>(g_y, g_wt[3], bo, out, 1.0f);
}

// ---------------------------------------------------------------------------
// Flash attention, tf32, causal. 256 threads (8 warps x 16 rows = 128 queries).
// KV tile 64, 2-stage cp.async. S and PV via mma; ldmatrix for K and P frags.
// grid: (T/128, H, B)
// ---------------------------------------------------------------------------
#define FKV_LD 68
#define FKV_SZ (64 * FKV_LD)   // 4352
#define FP_LD 68
#define FP_SZ (16 * FP_LD)     // 1088
#define PS_OFF (4 * FKV_SZ)    // after K[2], V[2]
#define FLASH_SMEM_BYTES ((4 * FKV_SZ + 8 * FP_SZ) * 4)   // 104448 B

__device__ __forceinline__ void flash_issue(u32 smbase, const u32* Kg, const u32* Vg,
                                            int j0, int buf, int tid)
{
    const int j = tid >> 2;
    const int cb = (tid & 3) * 16;
    const u32* ks = Kg + (size_t)(j0 + j) * CDIM + cb;
    const u32* vs = Vg + (size_t)(j0 + j) * CDIM + cb;
    const u32 kd = smbase + (u32)(buf * FKV_SZ + j * FKV_LD + cb) * 4;
    const u32 vd = smbase + (u32)(2 * FKV_SZ + buf * FKV_SZ + j * FKV_LD + cb) * 4;
#pragma unroll
    for (int i = 0; i < 4; i++) {
        cp16(kd + 16 * i, ks + 4 * i);
        cp16(vd + 16 * i, vs + 4 * i);
    }
}

__global__ __launch_bounds__(256) void flash_tf32_kernel()
{
    extern __shared__ u32 sm[];
    const u32 smbase = (u32)__cvta_generic_to_shared(sm);

    const int tid = threadIdx.x;
    const int lane = tid & 31;
    const int warp = tid >> 5;
    const int g = lane >> 2;
    const int t4 = lane & 3;
    const int lrow = (lane & 7) | ((lane & 16) >> 1);
    const int lcol = (lane & 8) >> 1;
    const int b = blockIdx.z;
    const int h = blockIdx.y;
    const int q0 = blockIdx.x * 128;
    const int qw = q0 + warp * 16;

    const u32* Kg = g_k + (size_t)(b * T_SEQ) * CDIM + h * D_HEAD;
    const u32* Vg = g_v + (size_t)(b * T_SEQ) * CDIM + h * D_HEAD;

    // Q fragments (already tf32, pre-scaled)
    const u32* Qg = g_q + (size_t)(b * T_SEQ + qw) * CDIM + h * D_HEAD;
    u32 qa[8][4];
#pragma unroll
    for (int kc = 0; kc < 8; kc++) {
        qa[kc][0] = Qg[(size_t)g * CDIM + kc * 8 + t4];
        qa[kc][1] = Qg[(size_t)(g + 8) * CDIM + kc * 8 + t4];
        qa[kc][2] = Qg[(size_t)g * CDIM + kc * 8 + t4 + 4];
        qa[kc][3] = Qg[(size_t)(g + 8) * CDIM + kc * 8 + t4 + 4];
    }

    float o[8][4];
#pragma unroll
    for (int nt = 0; nt < 8; nt++)
#pragma unroll
        for (int i = 0; i < 4; i++) o[nt][i] = 0.f;
    float m0 = -INFINITY, m1 = -INFINITY, l0 = 0.f, l1 = 0.f;

    const int ntiles = 2 * (blockIdx.x + 1);
    const u32 p_off = (u32)(PS_OFF + warp * FP_SZ);
    u32* Pw = sm + p_off;

    flash_issue(smbase, Kg, Vg, 0, 0, tid);
    CP_COMMIT();

#pragma unroll 1
    for (int tile = 0; tile < ntiles; tile++) {
        const int j0 = tile * 64;
        const int buf = tile & 1;
        if (tile + 1 < ntiles)
            flash_issue(smbase, Kg, Vg, j0 + 64, (tile + 1) & 1, tid);
        CP_COMMIT();
        CP_WAIT(1);
        __syncthreads();

        if (j0 <= qw + 15) {  // not fully masked for this warp
            // S = Q K^T
            float s[8][4];
#pragma unroll
            for (int nt = 0; nt < 8; nt++)
#pragma unroll
                for (int i = 0; i < 4; i++) s[nt][i] = 0.f;

            const u32 kbase = smbase + (u32)(buf * FKV_SZ + lrow * FKV_LD + lcol) * 4;
#pragma unroll
            for (int kc = 0; kc < 8; kc++) {
                u32 bf[8][2];
#pragma unroll
                for (int ntp = 0; ntp < 4; ntp++) {
                    u32 r0, r1, r2, r3;
                    ldsm4(r0, r1, r2, r3, kbase + (u32)(ntp * 16 * FKV_LD + kc * 8) * 4);
                    bf[2 * ntp][0] = r0; bf[2 * ntp][1] = r1;
                    bf[2 * ntp + 1][0] = r2; bf[2 * ntp + 1][1] = r3;
                }
#pragma unroll
                for (int nt = 0; nt < 8; nt++)
                    mma8(s[nt], qa[kc], bf[nt]);
            }

            // causal mask (partial tiles only)
            if (j0 + 63 > qw) {
#pragma unroll
                for (int nt = 0; nt < 8; nt++) {
                    const int cb = j0 + nt * 8 + 2 * t4;
                    if (cb     > qw + g)     s[nt][0] = -INFINITY;
                    if (cb + 1 > qw + g)     s[nt][1] = -INFINITY;
                    if (cb     > qw + g + 8) s[nt][2] = -INFINITY;
                    if (cb + 1 > qw + g + 8) s[nt][3] = -INFINITY;
                }
            }

            // online softmax
            float mx0 = -INFINITY, mx1 = -INFINITY;
#pragma unroll
            for (int nt = 0; nt < 8; nt++) {
                mx0 = fmaxf(mx0, fmaxf(s[nt][0], s[nt][1]));
                mx1 = fmaxf(mx1, fmaxf(s[nt][2], s[nt][3]));
            }
            mx0 = fmaxf(mx0, __shfl_xor_sync(0xffffffffu, mx0, 1));
            mx0 = fmaxf(mx0, __shfl_xor_sync(0xffffffffu, mx0, 2));
            mx1 = fmaxf(mx1, __shfl_xor_sync(0xffffffffu, mx1, 1));
            mx1 = fmaxf(mx1, __shfl_xor_sync(0xffffffffu, mx1, 2));

            const float mn0 = fmaxf(m0, mx0);
            const float mn1 = fmaxf(m1, mx1);
            const float cr0 = __expf(m0 - mn0);
            const float cr1 = __expf(m1 - mn1);
            float sum0 = 0.f, sum1 = 0.f;
#pragma unroll
            for (int nt = 0; nt < 8; nt++) {
                s[nt][0] = __expf(s[nt][0] - mn0);
                s[nt][1] = __expf(s[nt][1] - mn0);
                s[nt][2] = __expf(s[nt][2] - mn1);
                s[nt][3] = __expf(s[nt][3] - mn1);
                sum0 += s[nt][0] + s[nt][1];
                sum1 += s[nt][2] + s[nt][3];
            }
            sum0 += __shfl_xor_sync(0xffffffffu, sum0, 1);
            sum0 += __shfl_xor_sync(0xffffffffu, sum0, 2);
            sum1 += __shfl_xor_sync(0xffffffffu, sum1, 1);
            sum1 += __shfl_xor_sync(0xffffffffu, sum1, 2);
            l0 = l0 * cr0 + sum0;
            l1 = l1 * cr1 + sum1;
            m0 = mn0;
            m1 = mn1;
#pragma unroll
            for (int nt = 0; nt < 8; nt++) {
                o[nt][0] *= cr0;
                o[nt][1] *= cr0;
                o[nt][2] *= cr1;
                o[nt][3] *= cr1;
            }

            // stage P into warp-private smem
#pragma unroll
            for (int nt = 0; nt < 8; nt++) {
                uint2 v0, v1;
                v0.x = f2tf(s[nt][0]); v0.y = f2tf(s[nt][1]);
                v1.x = f2tf(s[nt][2]); v1.y = f2tf(s[nt][3]);
                *(uint2*)(Pw + g * FP_LD + nt * 8 + 2 * t4) = v0;
                *(uint2*)(Pw + (g + 8) * FP_LD + nt * 8 + 2 * t4) = v1;
            }
            __syncwarp();

            // O += P V
            const u32 pbase = smbase + (u32)(p_off + lrow * FP_LD + lcol) * 4;
            const u32 voff = (u32)(2 * FKV_SZ + buf * FKV_SZ);
#pragma unroll
            for (int kc = 0; kc < 8; kc++) {
                u32 r0, r1, r2, r3;
                ldsm4(r0, r1, r2, r3, pbase + (u32)(kc * 8) * 4);
                u32 af[4] = {r0, r2, r1, r3};
#pragma unroll
                for (int nt = 0; nt < 8; nt++) {
                    u32 bfv[2];
                    const u32* vp = sm + voff + (kc * 8 + t4) * FKV_LD + nt * 8 + g;
                    bfv[0] = vp[0];
                    bfv[1] = vp[4 * FKV_LD];
                    mma8(o[nt], af, bfv);
                }
            }
            __syncwarp();
        }
        __syncthreads();
    }

    // normalize + write tf32
    const float inv0 = 1.f / l0;
    const float inv1 = 1.f / l1;
    u32* Yg = g_y + (size_t)(b * T_SEQ + qw) * CDIM + h * D_HEAD;
#pragma unroll
    for (int nt = 0; nt < 8; nt++) {
        const int c = nt * 8 + 2 * t4;
        uint2 v0, v1;
        v0.x = f2tf(o[nt][0] * inv0); v0.y = f2tf(o[nt][1] * inv0);
        v1.x = f2tf(o[nt][2] * inv1); v1.y = f2tf(o[nt][3] * inv1);
        *(uint2*)(Yg + (size_t)g * CDIM + c) = v0;
        *(uint2*)(Yg + (size_t)(g + 8) * CDIM + c) = v1;
    }
}

// ---------------------------------------------------------------------------
extern "C" void kernel_launch(void* const* d_in, const int* in_sizes, int n_in,
                              void* d_out, int out_size)
{
    const float* x  = (const float*)d_in[0];
    const float* Wq = (const float*)d_in[1];
    const float* Wk = (const float*)d_in[2];
    const float* Wv = (const float*)d_in[3];
    const float* Wo = (const float*)d_in[4];
    const float* bo = (const float*)d_in[5];
    float* out = (float*)d_out;
    (void)in_sizes; (void)n_in; (void)out_size;

    static int inited = 0;
    if (!inited) {
        cudaFuncSetAttribute(qkv_gemm_kernel, cudaFuncAttributeMaxDynamicSharedMemorySize, GEMM_SMEM_BYTES);
        cudaFuncSetAttribute(out_gemm_kernel, cudaFuncAttributeMaxDynamicSharedMemorySize, GEMM_SMEM_BYTES);
        cudaFuncSetAttribute(flash_tf32_kernel, cudaFuncAttributeMaxDynamicSharedMemorySize, FLASH_SMEM_BYTES);
        inited = 1;
    }

    prep_x_kernel<<<2048, 256>>>(x);
    prep_w_kernel<<<dim3(32, 32, 4), dim3(32, 8)>>>(Wq, Wk, Wv, Wo);

    dim3 qkv_grid(CDIM / 128, MDIM / 128, 3);
    qkv_gemm_kernel<<<qkv_grid, 256, GEMM_SMEM_BYTES>>>();

    dim3 attn_grid(T_SEQ / 128, N_H, 2);
    flash_tf32_kernel<<<attn_grid, 256, FLASH_SMEM_BYTES>>>();

    dim3 out_grid(CDIM / 128, MDIM / 128);
    out_gemm_kernel<<<out_grid, 256, GEMM_SMEM_BYTES>>>(bo, out);
}

// round 4
// speedup vs baseline: 1.2125x; 1.2125x over previous
#include <cuda_runtime.h>
#include <math.h>

#define MDIM 4096
#define CDIM 1024
#define T_SEQ 2048
#define N_H 16
#define D_HEAD 64

typedef unsigned int u32;

// Scratch (device globals; allocation-free per harness rules)
__device__ u32 g_q[MDIM * CDIM];                     // tf32, pre-scaled 0.125
__device__ u32 g_k[MDIM * CDIM];                     // tf32
__device__ u32 g_v[MDIM * CDIM];                     // tf32
__device__ u32 g_vt[2 * N_H * D_HEAD * T_SEQ];       // tf32, [b,h,d,t]
__device__ u32 g_y[MDIM * CDIM];                     // tf32

// ---------------------------------------------------------------------------
// helpers
// ---------------------------------------------------------------------------
__device__ __forceinline__ u32 f2tf(float f) {
    u32 r;
    asm("cvt.rna.tf32.f32 %0, %1;" : "=r"(r) : "f"(f));
    return r;
}

__device__ __forceinline__ void mma8(float* d, const u32* a, const u32* b) {
    asm volatile(
        "mma.sync.aligned.m16n8k8.row.col.f32.tf32.tf32.f32 "
        "{%0,%1,%2,%3}, {%4,%5,%6,%7}, {%8,%9}, {%0,%1,%2,%3};"
        : "+f"(d[0]), "+f"(d[1]), "+f"(d[2]), "+f"(d[3])
        : "r"(a[0]), "r"(a[1]), "r"(a[2]), "r"(a[3]), "r"(b[0]), "r"(b[1]));
}

__device__ __forceinline__ void ldsm4(u32& r0, u32& r1, u32& r2, u32& r3, u32 addr) {
    asm volatile("ldmatrix.sync.aligned.m8n8.x4.shared.b16 {%0,%1,%2,%3}, [%4];"
                 : "=r"(r0), "=r"(r1), "=r"(r2), "=r"(r3) : "r"(addr));
}

__device__ __forceinline__ void cp16(u32 dst, const void* src) {
    asm volatile("cp.async.cg.shared.global [%0], [%1], 16;" :: "r"(dst), "l"(src));
}
#define CP_COMMIT() asm volatile("cp.async.commit_group;")
#define CP_WAIT(n)  asm volatile("cp.async.wait_group %0;" :: "n"(n))

// ---------------------------------------------------------------------------
// tf32 GEMM (R2-proven body): C[4096,1024] = A @ W (+bias)
// 128x128 tile, ktile 32, 256 thr (8 warps 4x2, warp tile 32x64), 2-buf smem.
// A smem [m][k] stride 36; B smem [k][n] stride 132.
// ATF: A is already tf32 u32. OUT_MODE 0: float+bias; 1: tf32 u32 * oscale.
// ---------------------------------------------------------------------------
#define AS_LD 36
#define BS_LD 132
#define AS_SZ (128 * AS_LD)
#define BS_SZ (32 * BS_LD)
#define GEMM_SMEM ((2 * (AS_SZ + BS_SZ)) * 4)

template <bool ATF, int OUT_MODE>
__device__ __forceinline__ void gemm_core(const void* __restrict__ Av,
                                          const float* __restrict__ W,
                                          const float* __restrict__ bias,
                                          void* __restrict__ Cv, float oscale)
{
    extern __shared__ u32 sm[];
    u32* As = sm;
    u32* Bs = sm + 2 * AS_SZ;

    const int tid = threadIdx.x;
    const int lane = tid & 31;
    const int warp = tid >> 5;
    const int wm = warp >> 1;
    const int wn = warp & 1;
    const int g = lane >> 2;
    const int t = lane & 3;

    const int row0 = blockIdx.y * 128;
    const int col0 = blockIdx.x * 128;

    const int a_row = tid >> 1;
    const int a_kq = (tid & 1) * 16;
    const float* Agf = (const float*)Av + (size_t)(row0 + a_row) * CDIM + a_kq;
    const u32* Agu = (const u32*)Av + (size_t)(row0 + a_row) * CDIM + a_kq;
    const int b_c4 = tid & 31;
    const int b_r = tid >> 5;
    const float* Bg = W + (size_t)b_r * CDIM + col0 + b_c4 * 4;

    float4 arf[4];
    uint4 aru[4];
    float4 br[4];

    float acc[2][8][4];
#pragma unroll
    for (int mt = 0; mt < 2; mt++)
#pragma unroll
        for (int nt = 0; nt < 8; nt++)
#pragma unroll
            for (int i = 0; i < 4; i++) acc[mt][nt][i] = 0.f;

    // prologue: load tile 0
    if (ATF) {
#pragma unroll
        for (int i = 0; i < 4; i++) aru[i] = *(const uint4*)(Agu + 4 * i);
    } else {
#pragma unroll
        for (int i = 0; i < 4; i++) arf[i] = *(const float4*)(Agf + 4 * i);
    }
#pragma unroll
    for (int i = 0; i < 4; i++) br[i] = *(const float4*)(Bg + (size_t)(8 * i) * CDIM);
    {
        u32* ap = As + a_row * AS_LD + a_kq;
#pragma unroll
        for (int i = 0; i < 4; i++) {
            uint4 v;
            if (ATF) v = aru[i];
            else {
                v.x = f2tf(arf[i].x); v.y = f2tf(arf[i].y);
                v.z = f2tf(arf[i].z); v.w = f2tf(arf[i].w);
            }
            *(uint4*)(ap + 4 * i) = v;
        }
        u32* bp = Bs + b_r * BS_LD + b_c4 * 4;
#pragma unroll
        for (int i = 0; i < 4; i++) {
            uint4 v;
            v.x = f2tf(br[i].x); v.y = f2tf(br[i].y); v.z = f2tf(br[i].z); v.w = f2tf(br[i].w);
            *(uint4*)(bp + (size_t)(8 * i) * BS_LD) = v;
        }
    }
    __syncthreads();

    for (int kt = 0; kt < 32; kt++) {
        const int cur = kt & 1;
        if (kt < 31) {
            const int k0 = (kt + 1) * 32;
            if (ATF) {
#pragma unroll
                for (int i = 0; i < 4; i++) aru[i] = *(const uint4*)(Agu + k0 + 4 * i);
            } else {
#pragma unroll
                for (int i = 0; i < 4; i++) arf[i] = *(const float4*)(Agf + k0 + 4 * i);
            }
#pragma unroll
            for (int i = 0; i < 4; i++)
                br[i] = *(const float4*)(Bg + (size_t)(k0 + 8 * i) * CDIM);
        }
        const u32* Ab = As + cur * AS_SZ + (wm * 32) * AS_LD;
        const u32* Bb = Bs + cur * BS_SZ + wn * 64;
#pragma unroll
        for (int kk = 0; kk < 4; kk++) {
            u32 af[2][4];
#pragma unroll
            for (int mt = 0; mt < 2; mt++) {
                const u32* p = Ab + (mt * 16 + g) * AS_LD + kk * 8 + t;
                af[mt][0] = p[0];
                af[mt][1] = p[8 * AS_LD];
                af[mt][2] = p[4];
                af[mt][3] = p[8 * AS_LD + 4];
            }
#pragma unroll
            for (int nt = 0; nt < 8; nt++) {
                u32 bf[2];
                const u32* p = Bb + (kk * 8 + t) * BS_LD + nt * 8 + g;
                bf[0] = p[0];
                bf[1] = p[4 * BS_LD];
#pragma unroll
                for (int mt = 0; mt < 2; mt++)
                    mma8(acc[mt][nt], af[mt], bf);
            }
        }
        if (kt < 31) {
            const int nbuf = (kt + 1) & 1;
            u32* ap = As + nbuf * AS_SZ + a_row * AS_LD + a_kq;
#pragma unroll
            for (int i = 0; i < 4; i++) {
                uint4 v;
                if (ATF) v = aru[i];
                else {
                    v.x = f2tf(arf[i].x); v.y = f2tf(arf[i].y);
                    v.z = f2tf(arf[i].z); v.w = f2tf(arf[i].w);
                }
                *(uint4*)(ap + 4 * i) = v;
            }
            u32* bp = Bs + nbuf * BS_SZ + b_r * BS_LD + b_c4 * 4;
#pragma unroll
            for (int i = 0; i < 4; i++) {
                uint4 v;
                v.x = f2tf(br[i].x); v.y = f2tf(br[i].y); v.z = f2tf(br[i].z); v.w = f2tf(br[i].w);
                *(uint4*)(bp + (size_t)(8 * i) * BS_LD) = v;
            }
            __syncthreads();
        }
    }

    // epilogue
#pragma unroll
    for (int mt = 0; mt < 2; mt++) {
#pragma unroll
        for (int nt = 0; nt < 8; nt++) {
            const int r = row0 + wm * 32 + mt * 16 + g;
            const int c = col0 + wn * 64 + nt * 8 + t * 2;
            if (OUT_MODE == 0) {
                float* C = (float*)Cv;
                const float b0 = bias[c], b1 = bias[c + 1];
                *(float2*)(C + (size_t)r * CDIM + c) =
                    make_float2(acc[mt][nt][0] + b0, acc[mt][nt][1] + b1);
                *(float2*)(C + (size_t)(r + 8) * CDIM + c) =
                    make_float2(acc[mt][nt][2] + b0, acc[mt][nt][3] + b1);
            } else {
                u32* C = (u32*)Cv;
                uint2 v0, v1;
                v0.x = f2tf(acc[mt][nt][0] * oscale);
                v0.y = f2tf(acc[mt][nt][1] * oscale);
                v1.x = f2tf(acc[mt][nt][2] * oscale);
                v1.y = f2tf(acc[mt][nt][3] * oscale);
                *(uint2*)(C + (size_t)r * CDIM + c) = v0;
                *(uint2*)(C + (size_t)(r + 8) * CDIM + c) = v1;
            }
        }
    }
}

__global__ __launch_bounds__(256) void qkv_gemm_kernel(const float* __restrict__ x,
                                                       const float* __restrict__ Wq,
                                                       const float* __restrict__ Wk,
                                                       const float* __restrict__ Wv)
{
    const int z = blockIdx.z;
    const float* W = (z == 0) ? Wq : (z == 1) ? Wk : Wv;
    u32* C = (z == 0) ? g_q : (z == 1) ? g_k : g_v;
    const float oscale = (z == 0) ? 0.125f : 1.0f;
    gemm_core<false, 1>(x, W, nullptr, C, oscale);
}

__global__ __launch_bounds__(256) void out_gemm_kernel(const float* __restrict__ Wo,
                                                       const float* __restrict__ bo,
                                                       float* __restrict__ out)
{
    gemm_core<true, 0>(g_y, Wo, bo, out, 1.0f);
}

// ---------------------------------------------------------------------------
// V transpose: g_v [b,t,h,d] (token-major) -> g_vt [b,h,d,t]
// ---------------------------------------------------------------------------
__global__ __launch_bounds__(256) void vt_kernel()
{
    __shared__ u32 tile[32][33];
    const int bh = blockIdx.z;          // b*16 + h
    const int b = bh >> 4, h = bh & 15;
    const int t0 = blockIdx.x * 32;
    const int d0 = blockIdx.y * 32;
    const int tx = threadIdx.x, ty = threadIdx.y;  // 32 x 8
#pragma unroll
    for (int i = 0; i < 32; i += 8)
        tile[ty + i][tx] = g_v[(size_t)(b * T_SEQ + t0 + ty + i) * CDIM + h * D_HEAD + d0 + tx];
    __syncthreads();
#pragma unroll
    for (int i = 0; i < 32; i += 8)
        g_vt[(size_t)(bh * D_HEAD + d0 + ty + i) * T_SEQ + t0 + tx] = tile[tx][ty + i];
}

// ---------------------------------------------------------------------------
// Flash attention, tf32, causal. 256 thr (8 warps x 16 q-rows = 128 queries).
// KV tile 64, 2-stage cp.async. K [kv][d] and Vt [d][kv] both n-major ->
// all mma B-fragments via ldmatrix. grid: (T/128, H, B), reversed x order.
// ---------------------------------------------------------------------------
#define FKV_LD 68
#define FKV_SZ (64 * FKV_LD)   // 4352
#define FP_LD 68
#define FP_SZ (16 * FP_LD)     // 1088
#define VT_OFF (2 * FKV_SZ)
#define PS_OFF (4 * FKV_SZ)
#define FLASH_SMEM_BYTES ((4 * FKV_SZ + 8 * FP_SZ) * 4)   // 104448 B

__device__ __forceinline__ void flash_issue(u32 smbase, const u32* Kg, const u32* Vtg,
                                            int j0, int buf, int tid)
{
    const int r = tid >> 2;             // K row (kv) / Vt row (d)
    const int cs = (tid & 3) * 16;      // col start (u32)
    const u32* ks = Kg + (size_t)(j0 + r) * CDIM + cs;
    const u32* vs = Vtg + (size_t)r * T_SEQ + j0 + cs;
    const u32 kd = smbase + (u32)(buf * FKV_SZ + r * FKV_LD + cs) * 4;
    const u32 vd = smbase + (u32)(VT_OFF + buf * FKV_SZ + r * FKV_LD + cs) * 4;
#pragma unroll
    for (int i = 0; i < 4; i++) {
        cp16(kd + 16 * i, ks + 4 * i);
        cp16(vd + 16 * i, vs + 4 * i);
    }
}

__global__ __launch_bounds__(256) void flash_tf32_kernel()
{
    extern __shared__ u32 sm[];
    const u32 smbase = (u32)__cvta_generic_to_shared(sm);

    const int tid = threadIdx.x;
    const int lane = tid & 31;
    const int warp = tid >> 5;
    const int g = lane >> 2;
    const int t4 = lane & 3;
    const int lrow = (lane & 7) | ((lane & 16) >> 1);
    const int lcol = (lane & 8) >> 1;
    const int b = blockIdx.z;
    const int h = blockIdx.y;
    const int qb = gridDim.x - 1 - blockIdx.x;   // heavy blocks first
    const int q0 = qb * 128;
    const int qw = q0 + warp * 16;

    const u32* Kg = g_k + (size_t)(b * T_SEQ) * CDIM + h * D_HEAD;
    const u32* Vtg = g_vt + (size_t)((b * N_H + h) * D_HEAD) * T_SEQ;

    // Q fragments (tf32, pre-scaled)
    const u32* Qg = g_q + (size_t)(b * T_SEQ + qw) * CDIM + h * D_HEAD;
    u32 qa[8][4];
#pragma unroll
    for (int kc = 0; kc < 8; kc++) {
        qa[kc][0] = Qg[(size_t)g * CDIM + kc * 8 + t4];
        qa[kc][1] = Qg[(size_t)(g + 8) * CDIM + kc * 8 + t4];
        qa[kc][2] = Qg[(size_t)g * CDIM + kc * 8 + t4 + 4];
        qa[kc][3] = Qg[(size_t)(g + 8) * CDIM + kc * 8 + t4 + 4];
    }

    float o[8][4];
#pragma unroll
    for (int nt = 0; nt < 8; nt++)
#pragma unroll
        for (int i = 0; i < 4; i++) o[nt][i] = 0.f;
    float m0 = -INFINITY, m1 = -INFINITY, l0 = 0.f, l1 = 0.f;

    const int ntiles = 2 * (qb + 1);
    const u32 p_off = (u32)(PS_OFF + warp * FP_SZ);
    u32* Pw = sm + p_off;

    flash_issue(smbase, Kg, Vtg, 0, 0, tid);
    CP_COMMIT();

#pragma unroll 1
    for (int tile = 0; tile < ntiles; tile++) {
        const int j0 = tile * 64;
        const int buf = tile & 1;
        if (tile + 1 < ntiles)
            flash_issue(smbase, Kg, Vtg, j0 + 64, (tile + 1) & 1, tid);
        CP_COMMIT();
        CP_WAIT(1);
        __syncthreads();

        if (j0 <= qw + 15) {
            // S = Q K^T
            float s[8][4];
#pragma unroll
            for (int nt = 0; nt < 8; nt++)
#pragma unroll
                for (int i = 0; i < 4; i++) s[nt][i] = 0.f;

            const u32 kbase = smbase + (u32)(buf * FKV_SZ + lrow * FKV_LD + lcol) * 4;
#pragma unroll
            for (int kc = 0; kc < 8; kc++) {
                u32 bf[8][2];
#pragma unroll
                for (int ntp = 0; ntp < 4; ntp++) {
                    u32 r0, r1, r2, r3;
                    ldsm4(r0, r1, r2, r3, kbase + (u32)(ntp * 16 * FKV_LD + kc * 8) * 4);
                    bf[2 * ntp][0] = r0; bf[2 * ntp][1] = r1;
                    bf[2 * ntp + 1][0] = r2; bf[2 * ntp + 1][1] = r3;
                }
#pragma unroll
                for (int nt = 0; nt < 8; nt++)
                    mma8(s[nt], qa[kc], bf[nt]);
            }

            // causal mask (partial tiles only)
            if (j0 + 63 > qw) {
#pragma unroll
                for (int nt = 0; nt < 8; nt++) {
                    const int cb = j0 + nt * 8 + 2 * t4;
                    if (cb     > qw + g)     s[nt][0] = -INFINITY;
                    if (cb + 1 > qw + g)     s[nt][1] = -INFINITY;
                    if (cb     > qw + g + 8) s[nt][2] = -INFINITY;
                    if (cb + 1 > qw + g + 8) s[nt][3] = -INFINITY;
                }
            }

            // online softmax (rows g, g+8)
            float mx0 = -INFINITY, mx1 = -INFINITY;
#pragma unroll
            for (int nt = 0; nt < 8; nt++) {
                mx0 = fmaxf(mx0, fmaxf(s[nt][0], s[nt][1]));
                mx1 = fmaxf(mx1, fmaxf(s[nt][2], s[nt][3]));
            }
            mx0 = fmaxf(mx0, __shfl_xor_sync(0xffffffffu, mx0, 1));
            mx0 = fmaxf(mx0, __shfl_xor_sync(0xffffffffu, mx0, 2));
            mx1 = fmaxf(mx1, __shfl_xor_sync(0xffffffffu, mx1, 1));
            mx1 = fmaxf(mx1, __shfl_xor_sync(0xffffffffu, mx1, 2));

            const float mn0 = fmaxf(m0, mx0);
            const float mn1 = fmaxf(m1, mx1);
            const float cr0 = __expf(m0 - mn0);
            const float cr1 = __expf(m1 - mn1);
            float sum0 = 0.f, sum1 = 0.f;
#pragma unroll
            for (int nt = 0; nt < 8; nt++) {
                s[nt][0] = __expf(s[nt][0] - mn0);
                s[nt][1] = __expf(s[nt][1] - mn0);
                s[nt][2] = __expf(s[nt][2] - mn1);
                s[nt][3] = __expf(s[nt][3] - mn1);
                sum0 += s[nt][0] + s[nt][1];
                sum1 += s[nt][2] + s[nt][3];
            }
            sum0 += __shfl_xor_sync(0xffffffffu, sum0, 1);
            sum0 += __shfl_xor_sync(0xffffffffu, sum0, 2);
            sum1 += __shfl_xor_sync(0xffffffffu, sum1, 1);
            sum1 += __shfl_xor_sync(0xffffffffu, sum1, 2);
            l0 = l0 * cr0 + sum0;
            l1 = l1 * cr1 + sum1;
            m0 = mn0;
            m1 = mn1;
#pragma unroll
            for (int nt = 0; nt < 8; nt++) {
                o[nt][0] *= cr0;
                o[nt][1] *= cr0;
                o[nt][2] *= cr1;
                o[nt][3] *= cr1;
            }

            // stage P (tf32) into warp-private smem
#pragma unroll
            for (int nt = 0; nt < 8; nt++) {
                uint2 v0, v1;
                v0.x = f2tf(s[nt][0]); v0.y = f2tf(s[nt][1]);
                v1.x = f2tf(s[nt][2]); v1.y = f2tf(s[nt][3]);
                *(uint2*)(Pw + g * FP_LD + nt * 8 + 2 * t4) = v0;
                *(uint2*)(Pw + (g + 8) * FP_LD + nt * 8 + 2 * t4) = v1;
            }
            __syncwarp();

            // O += P V   (Vt is n-major: B-fragments via ldmatrix)
            const u32 pbase = smbase + (u32)(p_off + lrow * FP_LD + lcol) * 4;
            const u32 vbase = smbase +
                (u32)(VT_OFF + buf * FKV_SZ + lrow * FKV_LD + lcol) * 4;
#pragma unroll
            for (int kc = 0; kc < 8; kc++) {
                u32 r0, r1, r2, r3;
                ldsm4(r0, r1, r2, r3, pbase + (u32)(kc * 8) * 4);
                u32 af[4] = {r0, r2, r1, r3};
                u32 bf[8][2];
#pragma unroll
                for (int ntp = 0; ntp < 4; ntp++) {
                    u32 q0r, q1r, q2r, q3r;
                    ldsm4(q0r, q1r, q2r, q3r, vbase + (u32)(ntp * 16 * FKV_LD + kc * 8) * 4);
                    bf[2 * ntp][0] = q0r; bf[2 * ntp][1] = q1r;
                    bf[2 * ntp + 1][0] = q2r; bf[2 * ntp + 1][1] = q3r;
                }
#pragma unroll
                for (int nt = 0; nt < 8; nt++)
                    mma8(o[nt], af, bf[nt]);
            }
            __syncwarp();
        }
        __syncthreads();
    }

    // normalize + write tf32
    const float inv0 = 1.f / l0;
    const float inv1 = 1.f / l1;
    u32* Yg = g_y + (size_t)(b * T_SEQ + qw) * CDIM + h * D_HEAD;
#pragma unroll
    for (int nt = 0; nt < 8; nt++) {
        const int c = nt * 8 + 2 * t4;
        uint2 v0, v1;
        v0.x = f2tf(o[nt][0] * inv0); v0.y = f2tf(o[nt][1] * inv0);
        v1.x = f2tf(o[nt][2] * inv1); v1.y = f2tf(o[nt][3] * inv1);
        *(uint2*)(Yg + (size_t)g * CDIM + c) = v0;
        *(uint2*)(Yg + (size_t)(g + 8) * CDIM + c) = v1;
    }
}

// ---------------------------------------------------------------------------
extern "C" void kernel_launch(void* const* d_in, const int* in_sizes, int n_in,
                              void* d_out, int out_size)
{
    const float* x  = (const float*)d_in[0];
    const float* Wq = (const float*)d_in[1];
    const float* Wk = (const float*)d_in[2];
    const float* Wv = (const float*)d_in[3];
    const float* Wo = (const float*)d_in[4];
    const float* bo = (const float*)d_in[5];
    float* out = (float*)d_out;
    (void)in_sizes; (void)n_in; (void)out_size;

    cudaFuncSetAttribute(qkv_gemm_kernel, cudaFuncAttributeMaxDynamicSharedMemorySize, GEMM_SMEM);
    cudaFuncSetAttribute(out_gemm_kernel, cudaFuncAttributeMaxDynamicSharedMemorySize, GEMM_SMEM);
    cudaFuncSetAttribute(flash_tf32_kernel, cudaFuncAttributeMaxDynamicSharedMemorySize, FLASH_SMEM_BYTES);

    dim3 qkv_grid(CDIM / 128, MDIM / 128, 3);
    qkv_gemm_kernel<<<qkv_grid, 256, GEMM_SMEM>>>(x, Wq, Wk, Wv);

    vt_kernel<<<dim3(T_SEQ / 32, D_HEAD / 32, 2 * N_H), dim3(32, 8)>>>();

    dim3 attn_grid(T_SEQ / 128, N_H, 2);
    flash_tf32_kernel<<<attn_grid, 256, FLASH_SMEM_BYTES>>>();

    dim3 out_grid(CDIM / 128, MDIM / 128);
    out_gemm_kernel<<<out_grid, 256, GEMM_SMEM>>>(Wo, bo, out);
}